// round 5
// baseline (speedup 1.0000x reference)
#include <cuda_runtime.h>

// RotationPerturbationLayer: the reference's dense [B,N,N] tent-weight einsum
// is mathematically exact bilinear sampling with zero padding:
//   tent(d) = relu(1-|d|) is nonzero only at the two bracketing integer taps,
//   so sum_p w[b,n,p] * img[c,p] = sum over <=4 neighbors of the rotated
//   source coordinate, with taps outside [0,W)x[0,H) contributing zero
//   (the reference only ever sums xs in [0,W), ys in [0,H)).
//
// B=8, C=3, H=W=64. One thread per (b, output pixel), all 3 channels.
// 32768 threads = 128 blocks x 256 -> single wave on 148 SMs.

#define BB 8
#define CC 3
#define HH 64
#define WW 64
#define NN (HH * WW)   // 4096

__global__ __launch_bounds__(256, 1)
void rotation_bilinear_kernel(const float* __restrict__ theta,
                              const float* __restrict__ image,
                              float* __restrict__ out)
{
    const int idx = blockIdx.x * blockDim.x + threadIdx.x;  // 0 .. B*N-1
    const int b = idx >> 12;        // / NN
    const int n = idx & (NN - 1);   // % NN
    const int y = n >> 6;           // / WW
    const int x = n & (WW - 1);     // % WW

    const float t = theta[b];       // theta is [B,1]; 8 distinct values, L1-broadcast
    float st, ct;
    __sincosf(t, &st, &ct);

    const float c_x = (WW - 1) * 0.5f;
    const float c_y = (HH - 1) * 0.5f;
    const float xr = (float)x - c_x;
    const float yr = (float)y - c_y;

    const float sx =  ct * xr + st * yr + c_x;
    const float sy = -st * xr + ct * yr + c_y;

    const float fx = floorf(sx);
    const float fy = floorf(sy);
    const int x0 = (int)fx;
    const int y0 = (int)fy;
    const int x1 = x0 + 1;
    const int y1 = y0 + 1;

    const float ax = sx - fx;       // tent weight toward x1
    const float ay = sy - fy;
    const float bx = 1.0f - ax;     // tent weight toward x0
    const float by = 1.0f - ay;

    const bool vx0 = (unsigned)x0 < (unsigned)WW;
    const bool vx1 = (unsigned)x1 < (unsigned)WW;
    const bool vy0 = (unsigned)y0 < (unsigned)HH;
    const bool vy1 = (unsigned)y1 < (unsigned)HH;

    float acc0 = 0.0f, acc1 = 0.0f, acc2 = 0.0f;

    // 4 taps x 3 channels; image planes are NN floats apart.
    if (vy0) {
        const int row = y0 * WW;
        if (vx0) {
            const float w = by * bx;
            const int p = row + x0;
            acc0 += w * __ldg(image + p);
            acc1 += w * __ldg(image + NN + p);
            acc2 += w * __ldg(image + 2 * NN + p);
        }
        if (vx1) {
            const float w = by * ax;
            const int p = row + x1;
            acc0 += w * __ldg(image + p);
            acc1 += w * __ldg(image + NN + p);
            acc2 += w * __ldg(image + 2 * NN + p);
        }
    }
    if (vy1) {
        const int row = y1 * WW;
        if (vx0) {
            const float w = ay * bx;
            const int p = row + x0;
            acc0 += w * __ldg(image + p);
            acc1 += w * __ldg(image + NN + p);
            acc2 += w * __ldg(image + 2 * NN + p);
        }
        if (vx1) {
            const float w = ay * ax;
            const int p = row + x1;
            acc0 += w * __ldg(image + p);
            acc1 += w * __ldg(image + NN + p);
            acc2 += w * __ldg(image + 2 * NN + p);
        }
    }

    // out layout [B, C, H, W]; per-channel writes are warp-contiguous.
    float* ob = out + b * (CC * NN) + n;
    ob[0]      = acc0;
    ob[NN]     = acc1;
    ob[2 * NN] = acc2;
}

extern "C" void kernel_launch(void* const* d_in, const int* in_sizes, int n_in,
                              void* d_out, int out_size)
{
    const float* theta = (const float*)d_in[0];  // [B,1] = 8 floats
    const float* image = (const float*)d_in[1];  // [C,H,W] = 12288 floats
    float* out = (float*)d_out;                  // [B,C,H,W] = 98304 floats

    const int total = BB * NN;                   // 32768
    rotation_bilinear_kernel<<<total / 256, 256>>>(theta, image, out);
}